// round 6
// baseline (speedup 1.0000x reference)
#include <cuda_runtime.h>
#include <cstdint>

#define B_ 8
#define T_ 1024
#define C_ 1024
#define H_ 16
#define HS 64

__device__ float g_q[(size_t)B_ * H_ * T_ * HS];
__device__ float g_k[(size_t)B_ * H_ * T_ * HS];
__device__ float g_v[(size_t)B_ * H_ * T_ * HS];
__device__ float g_xp[(size_t)B_ * T_ * C_];          // tf32-rounded X
__device__ float g_wt[(size_t)3 * H_ * HS * C_];      // tf32-rounded W^T, [mh*64+n][k]

__device__ __forceinline__ uint32_t f2tf32(float f) {
    uint32_t r; asm("cvt.rna.tf32.f32 %0, %1;" : "=r"(r) : "f"(f)); return r;
}
__device__ __forceinline__ float tf32f(float f) { return __uint_as_float(f2tf32(f)); }
__device__ __forceinline__ uint32_t smem_u32(const void* p) {
    uint32_t a;
    asm("{ .reg .u64 t; cvta.to.shared.u64 t, %1; cvt.u32.u64 %0, t; }" : "=r"(a) : "l"(p));
    return a;
}
static __device__ __forceinline__ void cp16(uint32_t dst, const void* src) {
    asm volatile("cp.async.cg.shared.global [%0], [%1], 16;" :: "r"(dst), "l"(src) : "memory");
}
#define CP_COMMIT() asm volatile("cp.async.commit_group;" ::: "memory")
#define CP_WAIT(n)  asm volatile("cp.async.wait_group %0;" :: "n"(n) : "memory")

__device__ __forceinline__ void mma8(float* d, const uint32_t* a, uint32_t b0, uint32_t b1) {
    asm volatile("mma.sync.aligned.m16n8k8.row.col.f32.tf32.tf32.f32 "
        "{%0,%1,%2,%3},{%4,%5,%6,%7},{%8,%9},{%0,%1,%2,%3};\n"
        : "+f"(d[0]), "+f"(d[1]), "+f"(d[2]), "+f"(d[3])
        : "r"(a[0]), "r"(a[1]), "r"(a[2]), "r"(a[3]), "r"(b0), "r"(b1));
}

// ---------------- prep ----------------
__global__ void xprep(const float* __restrict__ x) {
    size_t i = ((size_t)blockIdx.x * 256 + threadIdx.x) * 4;
    float4 v = *(const float4*)(x + i);
    v.x = tf32f(v.x); v.y = tf32f(v.y); v.z = tf32f(v.z); v.w = tf32f(v.w);
    *(float4*)(g_xp + i) = v;
}
__global__ void wprep(const float* __restrict__ Wq, const float* __restrict__ Wk,
                      const float* __restrict__ Wv) {
    __shared__ float t[64][65];
    int kt = blockIdx.x, mh = blockIdx.y;
    int m3 = mh >> 4, h = mh & 15;
    const float* W = (m3 == 0) ? Wq : ((m3 == 1) ? Wk : Wv);
    const float* src = W + (size_t)h * C_ * HS + (size_t)kt * 64 * HS;
    int tid = threadIdx.x;
#pragma unroll
    for (int i = 0; i < 16; i++) {
        int k = i * 4 + (tid >> 6), n = tid & 63;
        t[k][n] = src[(size_t)k * HS + n];
    }
    __syncthreads();
    float* dst = g_wt + (size_t)(mh * 64) * C_ + (size_t)kt * 64;
#pragma unroll
    for (int i = 0; i < 16; i++) {
        int n = i * 4 + (tid >> 6), kk = tid & 63;
        dst[(size_t)n * C_ + kk] = tf32f(t[kk][n]);
    }
}

// ---------------- proj3: 128x128 tile, 4 warps of 64x64, double-buffered ----------------
#define PAD 36
#define PTILE (128 * PAD)

__global__ __launch_bounds__(128) void proj3() {
    extern __shared__ float sm[];
    float* As = sm;                    // [2][128][PAD]
    float* Bs = sm + 2 * PTILE;        // [2][128][PAD]
    uint32_t sA = smem_u32(As), sB = smem_u32(Bs);

    const int tid = threadIdx.x, warp = tid >> 5, lane = tid & 31;
    const int g = lane >> 2, tg = lane & 3;
    const int wm = warp >> 1, wn = warp & 1;        // 2x2 warp grid, 64x64 each
    const int mtile = blockIdx.x, b = mtile >> 3, tt = mtile & 7;
    const int nb = blockIdx.y, m3 = nb >> 3, hp = nb & 7;

    const float* Arow = g_xp + (size_t)(b * T_ + tt * 128) * C_;
    const float* Brow = g_wt + (size_t)((m3 * 16 + hp * 2) * 64) * C_;

    float acc[4][8][4];
#pragma unroll
    for (int i = 0; i < 4; i++)
#pragma unroll
        for (int jn = 0; jn < 8; jn++)
#pragma unroll
            for (int e = 0; e < 4; e++) acc[i][jn][e] = 0.f;

    auto stage = [&](int buf, int k0) {
#pragma unroll
        for (int i = 0; i < 8; i++) {
            int fid = tid + i * 128;               // 0..1023
            int r = fid >> 3, cc = (fid & 7) * 4;
            cp16(sA + (buf * PTILE + r * PAD + cc) * 4, Arow + (size_t)r * C_ + k0 + cc);
            cp16(sB + (buf * PTILE + r * PAD + cc) * 4, Brow + (size_t)r * C_ + k0 + cc);
        }
        CP_COMMIT();
    };

    stage(0, 0);
    for (int kc = 0; kc < 32; kc++) {
        const int buf = kc & 1;
        if (kc < 31) { stage(buf ^ 1, (kc + 1) * 32); CP_WAIT(1); }
        else         { CP_WAIT(0); }
        __syncthreads();

        const float* A = As + buf * PTILE;
        const float* Bt = Bs + buf * PTILE;
#pragma unroll
        for (int ks = 0; ks < 4; ks++) {
            uint32_t a[4][4];
#pragma unroll
            for (int mt = 0; mt < 4; mt++) {
                int row = wm * 64 + mt * 16 + g;
                a[mt][0] = __float_as_uint(A[row * PAD + ks * 8 + tg]);
                a[mt][1] = __float_as_uint(A[(row + 8) * PAD + ks * 8 + tg]);
                a[mt][2] = __float_as_uint(A[row * PAD + ks * 8 + tg + 4]);
                a[mt][3] = __float_as_uint(A[(row + 8) * PAD + ks * 8 + tg + 4]);
            }
#pragma unroll
            for (int nt = 0; nt < 8; nt++) {
                int n = wn * 64 + nt * 8 + g;
                uint32_t b0 = __float_as_uint(Bt[n * PAD + ks * 8 + tg]);
                uint32_t b1 = __float_as_uint(Bt[n * PAD + ks * 8 + tg + 4]);
#pragma unroll
                for (int mt = 0; mt < 4; mt++) mma8(acc[mt][nt], a[mt], b0, b1);
            }
        }
        __syncthreads();
    }

    float* base = (m3 == 0) ? g_q : ((m3 == 1) ? g_k : g_v);
#pragma unroll
    for (int mt = 0; mt < 4; mt++) {
        int row = wm * 64 + mt * 16 + g;
        int t = tt * 128 + row;
#pragma unroll
        for (int nt = 0; nt < 8; nt++) {
            int col = wn * 64 + nt * 8 + tg * 2;
            int hsel = col >> 6, d = col & 63;
            int bh = b * H_ + hp * 2 + hsel;
            float* dst = base + ((size_t)bh * T_ + t) * HS + d;
            *(float2*)dst = make_float2(tf32f(acc[mt][nt][0]), tf32f(acc[mt][nt][1]));
            *(float2*)(dst + 8 * HS) = make_float2(tf32f(acc[mt][nt][2]), tf32f(acc[mt][nt][3]));
        }
    }
}

// ---------------- attn3: 128-row Q tile, 4 warps x 32 rows, double-buffered KV ----------------
#define KPAD 68
#define VPAD 72
#define KTS (64 * KPAD)
#define VTS (64 * VPAD)
#define KV_STRIDE (KTS + VTS)
#define PS_OFF (2 * KV_STRIDE)
#define PPAD 68
#define ATTN_SMEM ((PS_OFF + 128 * PPAD) * 4)

__global__ __launch_bounds__(128) void attn3(float* __restrict__ out)
{
    extern __shared__ float sm[];
    uint32_t sbase = smem_u32(sm);
    float* Ps = sm + PS_OFF;

    const int qt = (int)gridDim.x - 1 - (int)blockIdx.x;   // heavy blocks first
    const int bh = blockIdx.y, b = bh >> 4, h = bh & 15;
    const int tid = threadIdx.x, warp = tid >> 5, lane = tid & 31;
    const int g = lane >> 2, tg = lane & 3;
    const int r0 = warp * 32 + g;

    const float* qb = g_q + ((size_t)bh * T_ + qt * 128) * HS;
    const float* kb = g_k + (size_t)bh * T_ * HS;
    const float* vb = g_v + (size_t)bh * T_ * HS;

    // Q fragments: warp rows r0+mt*16, r0+mt*16+8 for mt=0,1; scaled by 1/8
    uint32_t qf[8][2][4];
#pragma unroll
    for (int ks = 0; ks < 8; ks++)
#pragma unroll
        for (int mt = 0; mt < 2; mt++) {
            int row = r0 + mt * 16;
            qf[ks][mt][0] = f2tf32(qb[(size_t)row * HS + ks * 8 + tg] * 0.125f);
            qf[ks][mt][1] = f2tf32(qb[(size_t)(row + 8) * HS + ks * 8 + tg] * 0.125f);
            qf[ks][mt][2] = f2tf32(qb[(size_t)row * HS + ks * 8 + tg + 4] * 0.125f);
            qf[ks][mt][3] = f2tf32(qb[(size_t)(row + 8) * HS + ks * 8 + tg + 4] * 0.125f);
        }

    float mrun[4] = {-1e30f, -1e30f, -1e30f, -1e30f};
    float lrun[4] = {0.f, 0.f, 0.f, 0.f};
    float oacc[2][8][4];
#pragma unroll
    for (int mt = 0; mt < 2; mt++)
#pragma unroll
        for (int nt = 0; nt < 8; nt++)
#pragma unroll
            for (int e = 0; e < 4; e++) oacc[mt][nt][e] = 0.f;

    auto stageKV = [&](int buf, int j) {
        const float* kp = kb + (size_t)j * 64 * HS;
        const float* vp = vb + (size_t)j * 64 * HS;
        uint32_t ko = sbase + (buf * KV_STRIDE) * 4;
        uint32_t vo = ko + KTS * 4;
#pragma unroll
        for (int i = 0; i < 8; i++) {
            int fid = tid + i * 128;
            int r = fid >> 4, cc = (fid & 15) * 4;
            cp16(ko + (r * KPAD + cc) * 4, kp + (size_t)r * HS + cc);
            cp16(vo + (r * VPAD + cc) * 4, vp + (size_t)r * HS + cc);
        }
        CP_COMMIT();
    };

    const int jmax = 2 * qt + 2;
    stageKV(0, 0);
    for (int j = 0; j < jmax; j++) {
        const int buf = j & 1;
        if (j + 1 < jmax) { stageKV(buf ^ 1, j + 1); CP_WAIT(1); }
        else              { CP_WAIT(0); }
        __syncthreads();

        const float* Ks = sm + buf * KV_STRIDE;
        const float* Vs = Ks + KTS;

        // S = Q K^T : 32 Q rows x 64 KV cols per warp
        float sacc[2][8][4];
#pragma unroll
        for (int mt = 0; mt < 2; mt++)
#pragma unroll
            for (int nt = 0; nt < 8; nt++)
#pragma unroll
                for (int e = 0; e < 4; e++) sacc[mt][nt][e] = 0.f;
#pragma unroll
        for (int ks = 0; ks < 8; ks++) {
#pragma unroll
            for (int nt = 0; nt < 8; nt++) {
                uint32_t b0 = __float_as_uint(Ks[(nt * 8 + g) * KPAD + ks * 8 + tg]);
                uint32_t b1 = __float_as_uint(Ks[(nt * 8 + g) * KPAD + ks * 8 + tg + 4]);
                mma8(sacc[0][nt], qf[ks][0], b0, b1);
                mma8(sacc[1][nt], qf[ks][1], b0, b1);
            }
        }

        // Causal mask (only on tiles that can cross the diagonal for this warp/mt)
#pragma unroll
        for (int mt = 0; mt < 2; mt++) {
            if (j * 64 + 63 > qt * 128 + warp * 32 + mt * 16) {
#pragma unroll
                for (int nt = 0; nt < 8; nt++)
#pragma unroll
                    for (int e = 0; e < 2; e++) {
                        int colg = j * 64 + nt * 8 + tg * 2 + e;
                        int rowg = qt * 128 + r0 + mt * 16;
                        if (colg > rowg)     sacc[mt][nt][e]     = -1e30f;
                        if (colg > rowg + 8) sacc[mt][nt][2 + e] = -1e30f;
                    }
            }
        }

        // In-register online softmax per (mt, half)
#pragma unroll
        for (int mt = 0; mt < 2; mt++) {
            float mx0 = -1e30f, mx1 = -1e30f;
#pragma unroll
            for (int nt = 0; nt < 8; nt++) {
                mx0 = fmaxf(mx0, fmaxf(sacc[mt][nt][0], sacc[mt][nt][1]));
                mx1 = fmaxf(mx1, fmaxf(sacc[mt][nt][2], sacc[mt][nt][3]));
            }
            mx0 = fmaxf(mx0, __shfl_xor_sync(0xffffffffu, mx0, 1));
            mx0 = fmaxf(mx0, __shfl_xor_sync(0xffffffffu, mx0, 2));
            mx1 = fmaxf(mx1, __shfl_xor_sync(0xffffffffu, mx1, 1));
            mx1 = fmaxf(mx1, __shfl_xor_sync(0xffffffffu, mx1, 2));

            float mn0 = fmaxf(mrun[mt * 2], mx0);
            float mn1 = fmaxf(mrun[mt * 2 + 1], mx1);
            float al0 = __expf(mrun[mt * 2] - mn0);
            float al1 = __expf(mrun[mt * 2 + 1] - mn1);
            float ls0 = 0.f, ls1 = 0.f;
#pragma unroll
            for (int nt = 0; nt < 8; nt++) {
                float p0 = __expf(sacc[mt][nt][0] - mn0);
                float p1 = __expf(sacc[mt][nt][1] - mn0);
                float p2 = __expf(sacc[mt][nt][2] - mn1);
                float p3 = __expf(sacc[mt][nt][3] - mn1);
                sacc[mt][nt][0] = p0; sacc[mt][nt][1] = p1;
                sacc[mt][nt][2] = p2; sacc[mt][nt][3] = p3;
                ls0 += p0 + p1; ls1 += p2 + p3;
            }
            ls0 += __shfl_xor_sync(0xffffffffu, ls0, 1);
            ls0 += __shfl_xor_sync(0xffffffffu, ls0, 2);
            ls1 += __shfl_xor_sync(0xffffffffu, ls1, 1);
            ls1 += __shfl_xor_sync(0xffffffffu, ls1, 2);
            lrun[mt * 2]     = al0 * lrun[mt * 2] + ls0;
            lrun[mt * 2 + 1] = al1 * lrun[mt * 2 + 1] + ls1;
            mrun[mt * 2] = mn0; mrun[mt * 2 + 1] = mn1;
#pragma unroll
            for (int nt = 0; nt < 8; nt++) {
                oacc[mt][nt][0] *= al0; oacc[mt][nt][1] *= al0;
                oacc[mt][nt][2] *= al1; oacc[mt][nt][3] *= al1;
            }
        }

        // Warp-private P transpose through smem
#pragma unroll
        for (int mt = 0; mt < 2; mt++)
#pragma unroll
            for (int nt = 0; nt < 8; nt++) {
                int cc = nt * 8 + tg * 2;
                int row = r0 + mt * 16;
                *(float2*)(&Ps[row * PPAD + cc]) = make_float2(sacc[mt][nt][0], sacc[mt][nt][1]);
                *(float2*)(&Ps[(row + 8) * PPAD + cc]) = make_float2(sacc[mt][nt][2], sacc[mt][nt][3]);
            }
        __syncwarp();

        // O += P V
#pragma unroll
        for (int ks = 0; ks < 8; ks++) {
            uint32_t pa[2][4];
#pragma unroll
            for (int mt = 0; mt < 2; mt++) {
                int row = r0 + mt * 16;
                pa[mt][0] = f2tf32(Ps[row * PPAD + ks * 8 + tg]);
                pa[mt][1] = f2tf32(Ps[(row + 8) * PPAD + ks * 8 + tg]);
                pa[mt][2] = f2tf32(Ps[row * PPAD + ks * 8 + tg + 4]);
                pa[mt][3] = f2tf32(Ps[(row + 8) * PPAD + ks * 8 + tg + 4]);
            }
#pragma unroll
            for (int nt = 0; nt < 8; nt++) {
                uint32_t b0 = __float_as_uint(Vs[(ks * 8 + tg) * VPAD + nt * 8 + g]);
                uint32_t b1 = __float_as_uint(Vs[(ks * 8 + tg + 4) * VPAD + nt * 8 + g]);
                mma8(oacc[0][nt], pa[0], b0, b1);
                mma8(oacc[1][nt], pa[1], b0, b1);
            }
        }
        __syncthreads();
    }

    // Normalize + write
#pragma unroll
    for (int mt = 0; mt < 2; mt++) {
        float inv0 = 1.0f / lrun[mt * 2];
        float inv1 = 1.0f / lrun[mt * 2 + 1];
        int row = qt * 128 + r0 + mt * 16;
        float* op = out + ((size_t)(b * T_ + row)) * (H_ * HS) + h * HS;
#pragma unroll
        for (int nt = 0; nt < 8; nt++) {
            int cc = nt * 8 + tg * 2;
            *(float2*)(op + cc) =
                make_float2(oacc[mt][nt][0] * inv0, oacc[mt][nt][1] * inv0);
            *(float2*)(op + (size_t)8 * (H_ * HS) + cc) =
                make_float2(oacc[mt][nt][2] * inv1, oacc[mt][nt][3] * inv1);
        }
    }
}

// ---------------------------------------------------------------------------
extern "C" void kernel_launch(void* const* d_in, const int* in_sizes, int n_in,
                              void* d_out, int out_size)
{
    const float* x  = (const float*)d_in[0];
    const float* Wq = (const float*)d_in[1];
    const float* Wk = (const float*)d_in[2];
    const float* Wv = (const float*)d_in[3];
    float* out = (float*)d_out;

    xprep<<<(B_ * T_ * C_) / 1024, 256>>>(x);
    wprep<<<dim3(16, 48), 256>>>(Wq, Wk, Wv);

    int psmem = 4 * PTILE * (int)sizeof(float);
    cudaFuncSetAttribute(proj3, cudaFuncAttributeMaxDynamicSharedMemorySize, psmem);
    proj3<<<dim3(64, 24), 128, psmem>>>();

    cudaFuncSetAttribute(attn3, cudaFuncAttributeMaxDynamicSharedMemorySize, ATTN_SMEM);
    attn3<<<dim3(T_ / 128, B_ * H_), 128, ATTN_SMEM>>>(out);
}

// round 7
// speedup vs baseline: 1.0145x; 1.0145x over previous
#include <cuda_runtime.h>
#include <cstdint>

#define B_ 8
#define T_ 1024
#define C_ 1024
#define H_ 16
#define HS 64

__device__ float g_q[(size_t)B_ * H_ * T_ * HS];
__device__ float g_k[(size_t)B_ * H_ * T_ * HS];
__device__ float g_v[(size_t)B_ * H_ * T_ * HS];
__device__ float g_xp[(size_t)B_ * T_ * C_];          // tf32-rounded X
__device__ float g_wt[(size_t)3 * H_ * HS * C_];      // tf32-rounded W^T, [mh*64+n][k]

__device__ __forceinline__ uint32_t f2tf32(float f) {
    uint32_t r; asm("cvt.rna.tf32.f32 %0, %1;" : "=r"(r) : "f"(f)); return r;
}
__device__ __forceinline__ float tf32f(float f) { return __uint_as_float(f2tf32(f)); }
__device__ __forceinline__ uint32_t smem_u32(const void* p) {
    uint32_t a;
    asm("{ .reg .u64 t; cvta.to.shared.u64 t, %1; cvt.u32.u64 %0, t; }" : "=r"(a) : "l"(p));
    return a;
}
static __device__ __forceinline__ void cp16(uint32_t dst, const void* src) {
    asm volatile("cp.async.cg.shared.global [%0], [%1], 16;" :: "r"(dst), "l"(src) : "memory");
}
#define CP_COMMIT() asm volatile("cp.async.commit_group;" ::: "memory")
#define CP_WAIT(n)  asm volatile("cp.async.wait_group %0;" :: "n"(n) : "memory")

__device__ __forceinline__ void mma8(float* d, const uint32_t* a, uint32_t b0, uint32_t b1) {
    asm volatile("mma.sync.aligned.m16n8k8.row.col.f32.tf32.tf32.f32 "
        "{%0,%1,%2,%3},{%4,%5,%6,%7},{%8,%9},{%0,%1,%2,%3};\n"
        : "+f"(d[0]), "+f"(d[1]), "+f"(d[2]), "+f"(d[3])
        : "r"(a[0]), "r"(a[1]), "r"(a[2]), "r"(a[3]), "r"(b0), "r"(b1));
}

// ---------------- prep ----------------
__global__ void xprep(const float* __restrict__ x) {
    size_t i = ((size_t)blockIdx.x * 256 + threadIdx.x) * 4;
    float4 v = *(const float4*)(x + i);
    v.x = tf32f(v.x); v.y = tf32f(v.y); v.z = tf32f(v.z); v.w = tf32f(v.w);
    *(float4*)(g_xp + i) = v;
}
__global__ void wprep(const float* __restrict__ Wq, const float* __restrict__ Wk,
                      const float* __restrict__ Wv) {
    __shared__ float t[64][65];
    int kt = blockIdx.x, mh = blockIdx.y;
    int m3 = mh >> 4, h = mh & 15;
    const float* W = (m3 == 0) ? Wq : ((m3 == 1) ? Wk : Wv);
    const float* src = W + (size_t)h * C_ * HS + (size_t)kt * 64 * HS;
    int tid = threadIdx.x;
#pragma unroll
    for (int i = 0; i < 16; i++) {
        int k = i * 4 + (tid >> 6), n = tid & 63;
        t[k][n] = src[(size_t)k * HS + n];
    }
    __syncthreads();
    float* dst = g_wt + (size_t)(mh * 64) * C_ + (size_t)kt * 64;
#pragma unroll
    for (int i = 0; i < 16; i++) {
        int n = i * 4 + (tid >> 6), kk = tid & 63;
        dst[(size_t)n * C_ + kk] = tf32f(t[kk][n]);
    }
}

// ---------------- proj4: 128x128 tile, 8 warps of 64x32, double-buffered ----------------
#define PAD 36
#define PTILE (128 * PAD)

__global__ __launch_bounds__(256, 2) void proj4() {
    extern __shared__ float sm[];
    float* As = sm;                    // [2][128][PAD]
    float* Bs = sm + 2 * PTILE;        // [2][128][PAD]
    uint32_t sA = smem_u32(As), sB = smem_u32(Bs);

    const int tid = threadIdx.x, warp = tid >> 5, lane = tid & 31;
    const int g = lane >> 2, tg = lane & 3;
    const int wm = warp >> 2, wn = warp & 3;        // 2x4 warp grid: 64 rows x 32 cols
    const int mtile = blockIdx.x, b = mtile >> 3, tt = mtile & 7;
    const int nb = blockIdx.y, m3 = nb >> 3, hp = nb & 7;

    const float* Arow = g_xp + (size_t)(b * T_ + tt * 128) * C_;
    const float* Brow = g_wt + (size_t)((m3 * 16 + hp * 2) * 64) * C_;

    float acc[4][4][4];
#pragma unroll
    for (int i = 0; i < 4; i++)
#pragma unroll
        for (int jn = 0; jn < 4; jn++)
#pragma unroll
            for (int e = 0; e < 4; e++) acc[i][jn][e] = 0.f;

    auto stage = [&](int buf, int k0) {
#pragma unroll
        for (int i = 0; i < 4; i++) {
            int fid = tid + i * 256;               // 0..1023
            int r = fid >> 3, cc = (fid & 7) * 4;
            cp16(sA + (buf * PTILE + r * PAD + cc) * 4, Arow + (size_t)r * C_ + k0 + cc);
            cp16(sB + (buf * PTILE + r * PAD + cc) * 4, Brow + (size_t)r * C_ + k0 + cc);
        }
        CP_COMMIT();
    };

    stage(0, 0);
    for (int kc = 0; kc < 32; kc++) {
        const int buf = kc & 1;
        if (kc < 31) { stage(buf ^ 1, (kc + 1) * 32); CP_WAIT(1); }
        else         { CP_WAIT(0); }
        __syncthreads();

        const float* A = As + buf * PTILE;
        const float* Bt = Bs + buf * PTILE;
#pragma unroll
        for (int ks = 0; ks < 4; ks++) {
            uint32_t a[4][4];
#pragma unroll
            for (int mt = 0; mt < 4; mt++) {
                int row = wm * 64 + mt * 16 + g;
                a[mt][0] = __float_as_uint(A[row * PAD + ks * 8 + tg]);
                a[mt][1] = __float_as_uint(A[(row + 8) * PAD + ks * 8 + tg]);
                a[mt][2] = __float_as_uint(A[row * PAD + ks * 8 + tg + 4]);
                a[mt][3] = __float_as_uint(A[(row + 8) * PAD + ks * 8 + tg + 4]);
            }
#pragma unroll
            for (int nt = 0; nt < 4; nt++) {
                int n = wn * 32 + nt * 8 + g;
                uint32_t b0 = __float_as_uint(Bt[n * PAD + ks * 8 + tg]);
                uint32_t b1 = __float_as_uint(Bt[n * PAD + ks * 8 + tg + 4]);
#pragma unroll
                for (int mt = 0; mt < 4; mt++) mma8(acc[mt][nt], a[mt], b0, b1);
            }
        }
        __syncthreads();
    }

    float* base = (m3 == 0) ? g_q : ((m3 == 1) ? g_k : g_v);
#pragma unroll
    for (int mt = 0; mt < 4; mt++) {
        int row = wm * 64 + mt * 16 + g;
        int t = tt * 128 + row;
#pragma unroll
        for (int nt = 0; nt < 4; nt++) {
            int col = wn * 32 + nt * 8 + tg * 2;
            int hsel = col >> 6, d = col & 63;
            int bh = b * H_ + hp * 2 + hsel;
            float* dst = base + ((size_t)bh * T_ + t) * HS + d;
            *(float2*)dst = make_float2(tf32f(acc[mt][nt][0]), tf32f(acc[mt][nt][1]));
            *(float2*)(dst + 8 * HS) = make_float2(tf32f(acc[mt][nt][2]), tf32f(acc[mt][nt][3]));
        }
    }
}

// ---------------- attn4: 128-row Q tile, 4 warps x 32 rows, exp2 softmax ----------------
#define KPAD 68
#define VPAD 72
#define KTS (64 * KPAD)
#define VTS (64 * VPAD)
#define KV_STRIDE (KTS + VTS)
#define PS_OFF (2 * KV_STRIDE)
#define PPAD 68
#define ATTN_SMEM ((PS_OFF + 128 * PPAD) * 4)
#define QSCALE (0.125f * 1.4426950408889634f)   // (1/sqrt(64)) * log2(e)

__global__ __launch_bounds__(128) void attn4(float* __restrict__ out)
{
    extern __shared__ float sm[];
    uint32_t sbase = smem_u32(sm);
    float* Ps = sm + PS_OFF;

    const int qt = (int)gridDim.x - 1 - (int)blockIdx.x;   // heavy blocks first
    const int bh = blockIdx.y, b = bh >> 4, h = bh & 15;
    const int tid = threadIdx.x, warp = tid >> 5, lane = tid & 31;
    const int g = lane >> 2, tg = lane & 3;
    const int r0 = warp * 32 + g;

    const float* qb = g_q + ((size_t)bh * T_ + qt * 128) * HS;
    const float* kb = g_k + (size_t)bh * T_ * HS;
    const float* vb = g_v + (size_t)bh * T_ * HS;

    uint32_t qf[8][2][4];
#pragma unroll
    for (int ks = 0; ks < 8; ks++)
#pragma unroll
        for (int mt = 0; mt < 2; mt++) {
            int row = r0 + mt * 16;
            qf[ks][mt][0] = f2tf32(qb[(size_t)row * HS + ks * 8 + tg] * QSCALE);
            qf[ks][mt][1] = f2tf32(qb[(size_t)(row + 8) * HS + ks * 8 + tg] * QSCALE);
            qf[ks][mt][2] = f2tf32(qb[(size_t)row * HS + ks * 8 + tg + 4] * QSCALE);
            qf[ks][mt][3] = f2tf32(qb[(size_t)(row + 8) * HS + ks * 8 + tg + 4] * QSCALE);
        }

    float mrun[4] = {-1e30f, -1e30f, -1e30f, -1e30f};
    float lrun[4] = {0.f, 0.f, 0.f, 0.f};
    float oacc[2][8][4];
#pragma unroll
    for (int mt = 0; mt < 2; mt++)
#pragma unroll
        for (int nt = 0; nt < 8; nt++)
#pragma unroll
            for (int e = 0; e < 4; e++) oacc[mt][nt][e] = 0.f;

    auto stageKV = [&](int buf, int j) {
        const float* kp = kb + (size_t)j * 64 * HS;
        const float* vp = vb + (size_t)j * 64 * HS;
        uint32_t ko = sbase + (buf * KV_STRIDE) * 4;
        uint32_t vo = ko + KTS * 4;
#pragma unroll
        for (int i = 0; i < 8; i++) {
            int fid = tid + i * 128;
            int r = fid >> 4, cc = (fid & 15) * 4;
            cp16(ko + (r * KPAD + cc) * 4, kp + (size_t)r * HS + cc);
            cp16(vo + (r * VPAD + cc) * 4, vp + (size_t)r * HS + cc);
        }
        CP_COMMIT();
    };

    const int jmax = 2 * qt + 2;
    stageKV(0, 0);
    for (int j = 0; j < jmax; j++) {
        const int buf = j & 1;
        if (j + 1 < jmax) { stageKV(buf ^ 1, j + 1); CP_WAIT(1); }
        else              { CP_WAIT(0); }
        __syncthreads();

        const float* Ks = sm + buf * KV_STRIDE;
        const float* Vs = Ks + KTS;

        float sacc[2][8][4];
#pragma unroll
        for (int mt = 0; mt < 2; mt++)
#pragma unroll
            for (int nt = 0; nt < 8; nt++)
#pragma unroll
                for (int e = 0; e < 4; e++) sacc[mt][nt][e] = 0.f;
#pragma unroll
        for (int ks = 0; ks < 8; ks++) {
#pragma unroll
            for (int nt = 0; nt < 8; nt++) {
                uint32_t b0 = __float_as_uint(Ks[(nt * 8 + g) * KPAD + ks * 8 + tg]);
                uint32_t b1 = __float_as_uint(Ks[(nt * 8 + g) * KPAD + ks * 8 + tg + 4]);
                mma8(sacc[0][nt], qf[ks][0], b0, b1);
                mma8(sacc[1][nt], qf[ks][1], b0, b1);
            }
        }

#pragma unroll
        for (int mt = 0; mt < 2; mt++) {
            if (j * 64 + 63 > qt * 128 + warp * 32 + mt * 16) {
#pragma unroll
                for (int nt = 0; nt < 8; nt++)
#pragma unroll
                    for (int e = 0; e < 2; e++) {
                        int colg = j * 64 + nt * 8 + tg * 2 + e;
                        int rowg = qt * 128 + r0 + mt * 16;
                        if (colg > rowg)     sacc[mt][nt][e]     = -1e30f;
                        if (colg > rowg + 8) sacc[mt][nt][2 + e] = -1e30f;
                    }
            }
        }

        // online softmax in log2 domain (scores already scaled by log2e)
#pragma unroll
        for (int mt = 0; mt < 2; mt++) {
            float mx0 = -1e30f, mx1 = -1e30f;
#pragma unroll
            for (int nt = 0; nt < 8; nt++) {
                mx0 = fmaxf(mx0, fmaxf(sacc[mt][nt][0], sacc[mt][nt][1]));
                mx1 = fmaxf(mx1, fmaxf(sacc[mt][nt][2], sacc[mt][nt][3]));
            }
            mx0 = fmaxf(mx0, __shfl_xor_sync(0xffffffffu, mx0, 1));
            mx0 = fmaxf(mx0, __shfl_xor_sync(0xffffffffu, mx0, 2));
            mx1 = fmaxf(mx1, __shfl_xor_sync(0xffffffffu, mx1, 1));
            mx1 = fmaxf(mx1, __shfl_xor_sync(0xffffffffu, mx1, 2));

            float mn0 = fmaxf(mrun[mt * 2], mx0);
            float mn1 = fmaxf(mrun[mt * 2 + 1], mx1);
            float al0 = exp2f(mrun[mt * 2] - mn0);
            float al1 = exp2f(mrun[mt * 2 + 1] - mn1);
            float ls0 = 0.f, ls1 = 0.f;
#pragma unroll
            for (int nt = 0; nt < 8; nt++) {
                float p0 = exp2f(sacc[mt][nt][0] - mn0);
                float p1 = exp2f(sacc[mt][nt][1] - mn0);
                float p2 = exp2f(sacc[mt][nt][2] - mn1);
                float p3 = exp2f(sacc[mt][nt][3] - mn1);
                sacc[mt][nt][0] = p0; sacc[mt][nt][1] = p1;
                sacc[mt][nt][2] = p2; sacc[mt][nt][3] = p3;
                ls0 += p0 + p1; ls1 += p2 + p3;
            }
            ls0 += __shfl_xor_sync(0xffffffffu, ls0, 1);
            ls0 += __shfl_xor_sync(0xffffffffu, ls0, 2);
            ls1 += __shfl_xor_sync(0xffffffffu, ls1, 1);
            ls1 += __shfl_xor_sync(0xffffffffu, ls1, 2);
            lrun[mt * 2]     = al0 * lrun[mt * 2] + ls0;
            lrun[mt * 2 + 1] = al1 * lrun[mt * 2 + 1] + ls1;
            mrun[mt * 2] = mn0; mrun[mt * 2 + 1] = mn1;
#pragma unroll
            for (int nt = 0; nt < 8; nt++) {
                oacc[mt][nt][0] *= al0; oacc[mt][nt][1] *= al0;
                oacc[mt][nt][2] *= al1; oacc[mt][nt][3] *= al1;
            }
        }

        // warp-private P transpose, pre-converted to tf32 bits
#pragma unroll
        for (int mt = 0; mt < 2; mt++)
#pragma unroll
            for (int nt = 0; nt < 8; nt++) {
                int cc = nt * 8 + tg * 2;
                int row = r0 + mt * 16;
                *(float2*)(&Ps[row * PPAD + cc]) = make_float2(
                    __uint_as_float(f2tf32(sacc[mt][nt][0])),
                    __uint_as_float(f2tf32(sacc[mt][nt][1])));
                *(float2*)(&Ps[(row + 8) * PPAD + cc]) = make_float2(
                    __uint_as_float(f2tf32(sacc[mt][nt][2])),
                    __uint_as_float(f2tf32(sacc[mt][nt][3])));
            }
        __syncwarp();

#pragma unroll
        for (int ks = 0; ks < 8; ks++) {
            uint32_t pa[2][4];
#pragma unroll
            for (int mt = 0; mt < 2; mt++) {
                int row = r0 + mt * 16;
                pa[mt][0] = __float_as_uint(Ps[row * PPAD + ks * 8 + tg]);
                pa[mt][1] = __float_as_uint(Ps[(row + 8) * PPAD + ks * 8 + tg]);
                pa[mt][2] = __float_as_uint(Ps[row * PPAD + ks * 8 + tg + 4]);
                pa[mt][3] = __float_as_uint(Ps[(row + 8) * PPAD + ks * 8 + tg + 4]);
            }
#pragma unroll
            for (int nt = 0; nt < 8; nt++) {
                uint32_t b0 = __float_as_uint(Vs[(ks * 8 + tg) * VPAD + nt * 8 + g]);
                uint32_t b1 = __float_as_uint(Vs[(ks * 8 + tg + 4) * VPAD + nt * 8 + g]);
                mma8(oacc[0][nt], pa[0], b0, b1);
                mma8(oacc[1][nt], pa[1], b0, b1);
            }
        }
        __syncthreads();
    }

#pragma unroll
    for (int mt = 0; mt < 2; mt++) {
        float inv0 = 1.0f / lrun[mt * 2];
        float inv1 = 1.0f / lrun[mt * 2 + 1];
        int row = qt * 128 + r0 + mt * 16;
        float* op = out + ((size_t)(b * T_ + row)) * (H_ * HS) + h * HS;
#pragma unroll
        for (int nt = 0; nt < 8; nt++) {
            int cc = nt * 8 + tg * 2;
            *(float2*)(op + cc) =
                make_float2(oacc[mt][nt][0] * inv0, oacc[mt][nt][1] * inv0);
            *(float2*)(op + (size_t)8 * (H_ * HS) + cc) =
                make_float2(oacc[mt][nt][2] * inv1, oacc[mt][nt][3] * inv1);
        }
    }
}

// ---------------------------------------------------------------------------
extern "C" void kernel_launch(void* const* d_in, const int* in_sizes, int n_in,
                              void* d_out, int out_size)
{
    const float* x  = (const float*)d_in[0];
    const float* Wq = (const float*)d_in[1];
    const float* Wk = (const float*)d_in[2];
    const float* Wv = (const float*)d_in[3];
    float* out = (float*)d_out;

    xprep<<<(B_ * T_ * C_) / 1024, 256>>>(x);
    wprep<<<dim3(16, 48), 256>>>(Wq, Wk, Wv);

    int psmem = 4 * PTILE * (int)sizeof(float);
    cudaFuncSetAttribute(proj4, cudaFuncAttributeMaxDynamicSharedMemorySize, psmem);
    proj4<<<dim3(64, 24), 256, psmem>>>();

    cudaFuncSetAttribute(attn4, cudaFuncAttributeMaxDynamicSharedMemorySize, ATTN_SMEM);
    attn4<<<dim3(T_ / 128, B_ * H_), 128, ATTN_SMEM>>>(out);
}

// round 8
// speedup vs baseline: 1.9638x; 1.9357x over previous
#include <cuda_runtime.h>
#include <cuda_fp16.h>
#include <cstdint>

#define B_ 8
#define T_ 1024
#define C_ 1024
#define H_ 16
#define HS 64

__device__ __half g_qh[(size_t)B_ * H_ * T_ * HS];   // Q pre-scaled by log2e/8
__device__ __half g_kh[(size_t)B_ * H_ * T_ * HS];
__device__ __half g_vh[(size_t)B_ * H_ * T_ * HS];
__device__ __half g_xh[(size_t)B_ * T_ * C_];        // fp16 X
__device__ __half g_wh[(size_t)3 * H_ * HS * C_];    // fp16 W^T, [(m3*16+h)*64+n][k]

#define QSCALE (0.125f * 1.4426950408889634f)        // (1/sqrt(64)) * log2(e)

__device__ __forceinline__ uint32_t smem_u32(const void* p) {
    uint32_t a;
    asm("{ .reg .u64 t; cvta.to.shared.u64 t, %1; cvt.u32.u64 %0, t; }" : "=r"(a) : "l"(p));
    return a;
}
static __device__ __forceinline__ void cp16(uint32_t dst, const void* src) {
    asm volatile("cp.async.cg.shared.global [%0], [%1], 16;" :: "r"(dst), "l"(src) : "memory");
}
#define CP_COMMIT() asm volatile("cp.async.commit_group;" ::: "memory")
#define CP_WAIT(n)  asm volatile("cp.async.wait_group %0;" :: "n"(n) : "memory")

// fp16 MMA: D(16x8,f32) += A(16x16,f16) * B(16x8,f16 col)
__device__ __forceinline__ void mma16(float* d, const uint32_t* a, uint32_t b0, uint32_t b1) {
    asm volatile("mma.sync.aligned.m16n8k16.row.col.f32.f16.f16.f32 "
        "{%0,%1,%2,%3},{%4,%5,%6,%7},{%8,%9},{%0,%1,%2,%3};\n"
        : "+f"(d[0]), "+f"(d[1]), "+f"(d[2]), "+f"(d[3])
        : "r"(a[0]), "r"(a[1]), "r"(a[2]), "r"(a[3]), "r"(b0), "r"(b1));
}
__device__ __forceinline__ void ldsm4(uint32_t* r, uint32_t addr) {
    asm volatile("ldmatrix.sync.aligned.m8n8.x4.shared.b16 {%0,%1,%2,%3}, [%4];"
        : "=r"(r[0]), "=r"(r[1]), "=r"(r[2]), "=r"(r[3]) : "r"(addr));
}
__device__ __forceinline__ void ldsm4t(uint32_t* r, uint32_t addr) {
    asm volatile("ldmatrix.sync.aligned.m8n8.x4.trans.shared.b16 {%0,%1,%2,%3}, [%4];"
        : "=r"(r[0]), "=r"(r[1]), "=r"(r[2]), "=r"(r[3]) : "r"(addr));
}

// ---------------- prep: convert X / transposed W to fp16 ----------------
__global__ void xprep(const float* __restrict__ x) {
    size_t i = ((size_t)blockIdx.x * 256 + threadIdx.x) * 4;
    float4 v = *(const float4*)(x + i);
    __half2 h0 = __floats2half2_rn(v.x, v.y);
    __half2 h1 = __floats2half2_rn(v.z, v.w);
    *(__half2*)(g_xh + i) = h0;
    *(__half2*)(g_xh + i + 2) = h1;
}
__global__ void wprep(const float* __restrict__ Wq, const float* __restrict__ Wk,
                      const float* __restrict__ Wv) {
    __shared__ float t[64][65];
    int kt = blockIdx.x, mh = blockIdx.y;
    int m3 = mh >> 4, h = mh & 15;
    const float* W = (m3 == 0) ? Wq : ((m3 == 1) ? Wk : Wv);
    const float* src = W + (size_t)h * C_ * HS + (size_t)kt * 64 * HS;
    int tid = threadIdx.x;
#pragma unroll
    for (int i = 0; i < 16; i++) {
        int k = i * 4 + (tid >> 6), n = tid & 63;
        t[k][n] = src[(size_t)k * HS + n];
    }
    __syncthreads();
    __half* dst = g_wh + (size_t)(mh * 64) * C_ + (size_t)kt * 64;
#pragma unroll
    for (int i = 0; i < 16; i++) {
        int n = i * 4 + (tid >> 6), kk = tid & 63;
        dst[(size_t)n * C_ + kk] = __float2half_rn(t[kk][n]);
    }
}

// ---------------- proj5: fp16 128x128 GEMM, ldmatrix, double-buffered ----------------
// smem rows: 64 halves data + 8 pad = 72 halves = 144 B (144/16=9 odd -> LDSM conflict-free)
#define RB 144
#define PTILE_B (128 * RB)        // 18432 B per tile buffer

__global__ __launch_bounds__(256, 2) void proj5() {
    extern __shared__ char smc[];
    uint32_t sb = smem_u32(smc);
    uint32_t sA = sb;                       // [2][128][RB]
    uint32_t sB = sb + 2 * PTILE_B;         // [2][128][RB]

    const int tid = threadIdx.x, warp = tid >> 5, lane = tid & 31;
    const int g = lane >> 2, tg = lane & 3;
    const int wm = warp >> 2, wn = warp & 3;            // 2x4: warp tile 64x32
    const int mtile = blockIdx.x, b = mtile >> 3, tt = mtile & 7;
    const int nb = blockIdx.y, m3 = nb >> 3, hp = nb & 7;

    const __half* Arow = g_xh + (size_t)(b * T_ + tt * 128) * C_;
    const __half* Brow = g_wh + (size_t)((m3 * 16 + hp * 2) * 64) * C_;

    // per-thread LDSM address parts
    const uint32_t a_row = wm * 64 + (lane & 15);       // + mt*16
    const uint32_t a_csel = (lane & 16) ? 16 : 0;       // k-halfblock
    const uint32_t b_row = wn * 32 + (lane & 7) + ((lane & 16) ? 8 : 0);  // + np*16
    const uint32_t b_csel = (lane & 8) ? 16 : 0;

    float acc[4][4][4];
#pragma unroll
    for (int i = 0; i < 4; i++)
#pragma unroll
        for (int jn = 0; jn < 4; jn++)
#pragma unroll
            for (int e = 0; e < 4; e++) acc[i][jn][e] = 0.f;

    auto stage = [&](int buf, int k0) {
#pragma unroll
        for (int i = 0; i < 4; i++) {
            int fid = tid + i * 256;                    // 0..1023
            int r = fid >> 3, cc = fid & 7;
            cp16(sA + buf * PTILE_B + r * RB + cc * 16, Arow + (size_t)r * C_ + k0 + cc * 8);
            cp16(sB + buf * PTILE_B + r * RB + cc * 16, Brow + (size_t)r * C_ + k0 + cc * 8);
        }
        CP_COMMIT();
    };

    stage(0, 0);
    for (int kc = 0; kc < 16; kc++) {                   // chunks of 64 k
        const int buf = kc & 1;
        if (kc < 15) { stage(buf ^ 1, (kc + 1) * 64); CP_WAIT(1); }
        else         { CP_WAIT(0); }
        __syncthreads();

        uint32_t Ab = sA + buf * PTILE_B;
        uint32_t Bb = sB + buf * PTILE_B;
#pragma unroll
        for (int ks = 0; ks < 4; ks++) {                // k16 steps
            uint32_t a[4][4];
#pragma unroll
            for (int mt = 0; mt < 4; mt++)
                ldsm4(a[mt], Ab + (a_row + mt * 16) * RB + ks * 32 + a_csel);
            uint32_t bb[2][4];
#pragma unroll
            for (int np = 0; np < 2; np++)
                ldsm4(bb[np], Bb + (b_row + np * 16) * RB + ks * 32 + b_csel);
#pragma unroll
            for (int np = 0; np < 2; np++)
#pragma unroll
                for (int half = 0; half < 2; half++) {
                    int nt = np * 2 + half;
                    uint32_t b0 = bb[np][half * 2], b1 = bb[np][half * 2 + 1];
#pragma unroll
                    for (int mt = 0; mt < 4; mt++) mma16(acc[mt][nt], a[mt], b0, b1);
                }
        }
        __syncthreads();
    }

    // Epilogue: write fp16 q/k/v (Q pre-scaled by QSCALE)
    __half* base = (m3 == 0) ? g_qh : ((m3 == 1) ? g_kh : g_vh);
    const float osc = (m3 == 0) ? QSCALE : 1.0f;
#pragma unroll
    for (int mt = 0; mt < 4; mt++) {
        int row = wm * 64 + mt * 16 + g;
        int t = tt * 128 + row;
#pragma unroll
        for (int nt = 0; nt < 4; nt++) {
            int col = wn * 32 + nt * 8 + tg * 2;
            int hsel = col >> 6, d = col & 63;
            int bh = b * H_ + hp * 2 + hsel;
            __half* dst = base + ((size_t)bh * T_ + t) * HS + d;
            *(__half2*)dst = __floats2half2_rn(acc[mt][nt][0] * osc, acc[mt][nt][1] * osc);
            *(__half2*)(dst + 8 * HS) = __floats2half2_rn(acc[mt][nt][2] * osc, acc[mt][nt][3] * osc);
        }
    }
}

// ---------------- attn5: fp16 flash attention, ldmatrix everywhere ----------------
#define KB_T (64 * RB)                    // 9216 B per K or V tile
#define KV_STRIDE (2 * KB_T)
#define PS_OFF (2 * KV_STRIDE)            // 36864
#define ATTN_SMEM (PS_OFF + 128 * RB)     // + P tile 18432 = 55296 B

__global__ __launch_bounds__(128) void attn5(float* __restrict__ out)
{
    extern __shared__ char smc[];
    uint32_t sb = smem_u32(smc);

    const int qt = (int)gridDim.x - 1 - (int)blockIdx.x;   // heavy blocks first
    const int bh = blockIdx.y, b = bh >> 4, h = bh & 15;
    const int tid = threadIdx.x, warp = tid >> 5, lane = tid & 31;
    const int g = lane >> 2, tg = lane & 3;
    const int r0 = warp * 32 + g;

    const __half* qb = g_qh + ((size_t)bh * T_ + qt * 128) * HS;
    const __half* kb = g_kh + (size_t)bh * T_ * HS;
    const __half* vb = g_vh + (size_t)bh * T_ * HS;

    // Q fragments (pre-scaled at proj): rows r0+mt*16 (+8), k16 steps
    uint32_t qf[4][2][4];
#pragma unroll
    for (int ks = 0; ks < 4; ks++)
#pragma unroll
        for (int mt = 0; mt < 2; mt++) {
            int row = r0 + mt * 16;
            qf[ks][mt][0] = *(const uint32_t*)(qb + (size_t)row * HS + ks * 16 + 2 * tg);
            qf[ks][mt][1] = *(const uint32_t*)(qb + (size_t)(row + 8) * HS + ks * 16 + 2 * tg);
            qf[ks][mt][2] = *(const uint32_t*)(qb + (size_t)row * HS + ks * 16 + 8 + 2 * tg);
            qf[ks][mt][3] = *(const uint32_t*)(qb + (size_t)(row + 8) * HS + ks * 16 + 8 + 2 * tg);
        }

    float mrun[4] = {-1e30f, -1e30f, -1e30f, -1e30f};
    float lrun[4] = {0.f, 0.f, 0.f, 0.f};
    float oacc[2][8][4];
#pragma unroll
    for (int mt = 0; mt < 2; mt++)
#pragma unroll
        for (int nt = 0; nt < 8; nt++)
#pragma unroll
            for (int e = 0; e < 4; e++) oacc[mt][nt][e] = 0.f;

    auto stageKV = [&](int buf, int j) {
        const __half* kp = kb + (size_t)j * 64 * HS;
        const __half* vp = vb + (size_t)j * 64 * HS;
        uint32_t ko = sb + buf * KV_STRIDE;
        uint32_t vo = ko + KB_T;
#pragma unroll
        for (int i = 0; i < 4; i++) {
            int fid = tid + i * 128;                     // 0..511
            int r = fid >> 3, cc = fid & 7;
            cp16(ko + r * RB + cc * 16, kp + (size_t)r * HS + cc * 8);
            cp16(vo + r * RB + cc * 16, vp + (size_t)r * HS + cc * 8);
        }
        CP_COMMIT();
    };

    // LDSM address parts
    const uint32_t kb_row = (lane & 7) + ((lane & 16) ? 8 : 0);  // + ntp*16 (token)
    const uint32_t kb_csel = (lane & 8) ? 16 : 0;
    const uint32_t pa_row = warp * 32 + (lane & 15);             // + mt*16
    const uint32_t pa_csel = (lane & 16) ? 16 : 0;
    const uint32_t vt_row = (lane & 7) + ((lane & 8) ? 8 : 0);   // + ks*16 (token)
    const uint32_t vt_col = (lane & 16) ? 16 : 0;                // + ntp*32 bytes

    const int jmax = 2 * qt + 2;
    stageKV(0, 0);
    for (int j = 0; j < jmax; j++) {
        const int buf = j & 1;
        if (j + 1 < jmax) { stageKV(buf ^ 1, j + 1); CP_WAIT(1); }
        else              { CP_WAIT(0); }
        __syncthreads();

        uint32_t Kb = sb + buf * KV_STRIDE;
        uint32_t Vb = Kb + KB_T;

        // S = Q K^T
        float sacc[2][8][4];
#pragma unroll
        for (int mt = 0; mt < 2; mt++)
#pragma unroll
            for (int nt = 0; nt < 8; nt++)
#pragma unroll
                for (int e = 0; e < 4; e++) sacc[mt][nt][e] = 0.f;
#pragma unroll
        for (int ks = 0; ks < 4; ks++) {
#pragma unroll
            for (int ntp = 0; ntp < 4; ntp++) {
                uint32_t kk[4];
                ldsm4(kk, Kb + (kb_row + ntp * 16) * RB + ks * 32 + kb_csel);
#pragma unroll
                for (int half = 0; half < 2; half++) {
                    int nt = ntp * 2 + half;
                    mma16(sacc[0][nt], qf[ks][0], kk[half * 2], kk[half * 2 + 1]);
                    mma16(sacc[1][nt], qf[ks][1], kk[half * 2], kk[half * 2 + 1]);
                }
            }
        }

        // causal mask
#pragma unroll
        for (int mt = 0; mt < 2; mt++) {
            if (j * 64 + 63 > qt * 128 + warp * 32 + mt * 16) {
#pragma unroll
                for (int nt = 0; nt < 8; nt++)
#pragma unroll
                    for (int e = 0; e < 2; e++) {
                        int colg = j * 64 + nt * 8 + tg * 2 + e;
                        int rowg = qt * 128 + r0 + mt * 16;
                        if (colg > rowg)     sacc[mt][nt][e]     = -1e30f;
                        if (colg > rowg + 8) sacc[mt][nt][2 + e] = -1e30f;
                    }
            }
        }

        // online softmax, log2 domain
#pragma unroll
        for (int mt = 0; mt < 2; mt++) {
            float mx0 = -1e30f, mx1 = -1e30f;
#pragma unroll
            for (int nt = 0; nt < 8; nt++) {
                mx0 = fmaxf(mx0, fmaxf(sacc[mt][nt][0], sacc[mt][nt][1]));
                mx1 = fmaxf(mx1, fmaxf(sacc[mt][nt][2], sacc[mt][nt][3]));
            }
            mx0 = fmaxf(mx0, __shfl_xor_sync(0xffffffffu, mx0, 1));
            mx0 = fmaxf(mx0, __shfl_xor_sync(0xffffffffu, mx0, 2));
            mx1 = fmaxf(mx1, __shfl_xor_sync(0xffffffffu, mx1, 1));
            mx1 = fmaxf(mx1, __shfl_xor_sync(0xffffffffu, mx1, 2));

            float mn0 = fmaxf(mrun[mt * 2], mx0);
            float mn1 = fmaxf(mrun[mt * 2 + 1], mx1);
            float al0 = exp2f(mrun[mt * 2] - mn0);
            float al1 = exp2f(mrun[mt * 2 + 1] - mn1);
            float ls0 = 0.f, ls1 = 0.f;
#pragma unroll
            for (int nt = 0; nt < 8; nt++) {
                float p0 = exp2f(sacc[mt][nt][0] - mn0);
                float p1 = exp2f(sacc[mt][nt][1] - mn0);
                float p2 = exp2f(sacc[mt][nt][2] - mn1);
                float p3 = exp2f(sacc[mt][nt][3] - mn1);
                sacc[mt][nt][0] = p0; sacc[mt][nt][1] = p1;
                sacc[mt][nt][2] = p2; sacc[mt][nt][3] = p3;
                ls0 += p0 + p1; ls1 += p2 + p3;
            }
            ls0 += __shfl_xor_sync(0xffffffffu, ls0, 1);
            ls0 += __shfl_xor_sync(0xffffffffu, ls0, 2);
            ls1 += __shfl_xor_sync(0xffffffffu, ls1, 1);
            ls1 += __shfl_xor_sync(0xffffffffu, ls1, 2);
            lrun[mt * 2]     = al0 * lrun[mt * 2] + ls0;
            lrun[mt * 2 + 1] = al1 * lrun[mt * 2 + 1] + ls1;
            mrun[mt * 2] = mn0; mrun[mt * 2 + 1] = mn1;
#pragma unroll
            for (int nt = 0; nt < 8; nt++) {
                oacc[mt][nt][0] *= al0; oacc[mt][nt][1] *= al0;
                oacc[mt][nt][2] *= al1; oacc[mt][nt][3] *= al1;
            }
        }

        // P -> smem as fp16 (warp-private region)
        {
            char* Pp = smc + PS_OFF;
#pragma unroll
            for (int mt = 0; mt < 2; mt++)
#pragma unroll
                for (int nt = 0; nt < 8; nt++) {
                    int row = r0 + mt * 16;
                    int cc = nt * 8 + tg * 2;
                    *(__half2*)(Pp + row * RB + cc * 2) =
                        __floats2half2_rn(sacc[mt][nt][0], sacc[mt][nt][1]);
                    *(__half2*)(Pp + (row + 8) * RB + cc * 2) =
                        __floats2half2_rn(sacc[mt][nt][2], sacc[mt][nt][3]);
                }
        }
        __syncwarp();

        // O += P V   (P via LDSM, V via LDSM.trans from row-major)
        uint32_t Pb = sb + PS_OFF;
#pragma unroll
        for (int ks = 0; ks < 4; ks++) {
            uint32_t pa[2][4];
#pragma unroll
            for (int mt = 0; mt < 2; mt++)
                ldsm4(pa[mt], Pb + (pa_row + mt * 16) * RB + ks * 32 + pa_csel);
#pragma unroll
            for (int ntp = 0; ntp < 4; ntp++) {
                uint32_t vv[4];
                ldsm4t(vv, Vb + (vt_row + ks * 16) * RB + ntp * 32 + vt_col);
#pragma unroll
                for (int half = 0; half < 2; half++) {
                    int nt = ntp * 2 + half;
                    mma16(oacc[0][nt], pa[0], vv[half * 2], vv[half * 2 + 1]);
                    mma16(oacc[1][nt], pa[1], vv[half * 2], vv[half * 2 + 1]);
                }
            }
        }
        __syncthreads();
    }

#pragma unroll
    for (int mt = 0; mt < 2; mt++) {
        float inv0 = 1.0f / lrun[mt * 2];
        float inv1 = 1.0f / lrun[mt * 2 + 1];
        int row = qt * 128 + r0 + mt * 16;
        float* op = out + ((size_t)(b * T_ + row)) * (H_ * HS) + h * HS;
#pragma unroll
        for (int nt = 0; nt < 8; nt++) {
            int cc = nt * 8 + tg * 2;
            *(float2*)(op + cc) =
                make_float2(oacc[mt][nt][0] * inv0, oacc[mt][nt][1] * inv0);
            *(float2*)(op + (size_t)8 * (H_ * HS) + cc) =
                make_float2(oacc[mt][nt][2] * inv1, oacc[mt][nt][3] * inv1);
        }
    }
}

// ---------------------------------------------------------------------------
extern "C" void kernel_launch(void* const* d_in, const int* in_sizes, int n_in,
                              void* d_out, int out_size)
{
    const float* x  = (const float*)d_in[0];
    const float* Wq = (const float*)d_in[1];
    const float* Wk = (const float*)d_in[2];
    const float* Wv = (const float*)d_in[3];
    float* out = (float*)d_out;

    xprep<<<(B_ * T_ * C_) / 1024, 256>>>(x);
    wprep<<<dim3(16, 48), 256>>>(Wq, Wk, Wv);

    int psmem = 4 * PTILE_B;                    // 73728 B
    cudaFuncSetAttribute(proj5, cudaFuncAttributeMaxDynamicSharedMemorySize, psmem);
    proj5<<<dim3(64, 24), 256, psmem>>>();

    cudaFuncSetAttribute(attn5, cudaFuncAttributeMaxDynamicSharedMemorySize, ATTN_SMEM);
    attn5<<<dim3(T_ / 128, B_ * H_), 128, ATTN_SMEM>>>(out);
}